// round 9
// baseline (speedup 1.0000x reference)
#include <cuda_runtime.h>
#include <cuda_fp16.h>
#include <cstdint>

// DFT_10316511445664 — batched 100-pt DFT as folded fp16 split mma.sync GEMM.
// out[B,100] = x @ W. Column symmetry: with A- = x*(-1)^k (sign-flip of odd-k
// halves), the 52-col folded B yields bins j (A+) and 50-j (A-), halving B-LDS.
// A staged per-warp in smem (coalesced LDG.128, conflict-free LDS.32 frags).
// Mirror-side (M) outputs land on odd column offsets -> scalar stores.

#define NFFT 100
#define MT   128
#define BT   256
#define GRID 444       // 148 SMs * 3 CTAs
#define NKS  7
#define NNT  7         // folded 52 cols padded to 56

// smem: [0,12544) B frags uint2[NKS][NNT][32]; then per-warp A stage 6656B
// (hi [16][52] u32 f16x2-words, lo at +832 words; words 50,51 = zero pad).
#define B_BYTES    12544
#define WARP_WORDS 52
#define SMEM_TOTAL (B_BYTES + 8 * 6656)

__device__ __forceinline__ float wvalf(int k, int c) {
    if (k >= NFFT || c >= 52) return 0.f;
    const bool re = (c < 26);
    const int j = re ? c : c - 26;
    const int m = (k * j) % 100;
    float s, cs;
    sincospif((float)m * 0.02f, &s, &cs);
    float t = re ? cs : -s;            // re: cos ; im: -sin
    if (k & 1) t = -t;                 // fftshift (-1)^k
    return t * 0.01f;                  // 1/N_FFT
}

__device__ __forceinline__ void mma16816(uint32_t* d, const uint4& a, const uint2& b) {
    asm volatile(
        "mma.sync.aligned.m16n8k16.row.col.f32.f16.f16.f32 "
        "{%0,%1,%2,%3}, {%4,%5,%6,%7}, {%8,%9}, {%0,%1,%2,%3};"
        : "+r"(d[0]), "+r"(d[1]), "+r"(d[2]), "+r"(d[3])
        : "r"(a.x), "r"(a.y), "r"(a.z), "r"(a.w), "r"(b.x), "r"(b.y));
}

// float2 -> fp16x2 hi + fp16x2 lo (low 16 bits = first/even element)
__device__ __forceinline__ void split2(float2 v, uint32_t& hi, uint32_t& lo) {
    asm("cvt.rn.f16x2.f32 %0, %1, %2;" : "=r"(hi) : "f"(v.y), "f"(v.x));
    float h0, h1;
    asm("{ .reg .b16 a, b; mov.b32 {a, b}, %2; cvt.f32.f16 %0, a; cvt.f32.f16 %1, b; }"
        : "=f"(h0), "=f"(h1) : "r"(hi));
    asm("cvt.rn.f16x2.f32 %0, %1, %2;" : "=r"(lo) : "f"(v.y - h1), "f"(v.x - h0));
}

__device__ __forceinline__ void st2(float* p, float a, float b) {
    *reinterpret_cast<float2*>(p) = make_float2(a, b);
}

__global__ __launch_bounds__(BT, 3) void dft_mma(const float* __restrict__ x,
                                                 float* __restrict__ xfft,
                                                 float* __restrict__ logp,
                                                 int ntiles) {
    extern __shared__ char smem[];
    uint2 (*bsh)[NNT][32] = reinterpret_cast<uint2 (*)[NNT][32]>(smem);

    const int tid  = threadIdx.x;
    const int wid  = tid >> 5;
    const int lane = tid & 31;
    const int g    = lane >> 2, tg = lane & 3;

    uint32_t* const whi = reinterpret_cast<uint32_t*>(smem + B_BYTES + wid * 6656);
    uint32_t* const wlo = whi + 16 * WARP_WORDS;

    // Build folded B fragments in-CTA (fp32 sincospi; error << fp16 rounding).
    for (int i = tid; i < NKS * NNT * 32; i += BT) {
        const int ln = i & 31, t = i >> 5;
        const int nt = t % NNT, ks = t / NNT;
        const int c = 8 * nt + (ln >> 2), tt = ln & 3;
        uint32_t v[2];
#pragma unroll
        for (int h = 0; h < 2; ++h) {
            uint32_t p = 0;
#pragma unroll
            for (int e = 0; e < 2; ++e) {
                const int k = 16 * ks + 2 * tt + 8 * h + e;
                p |= (uint32_t)__half_as_ushort(__float2half_rn(wvalf(k, c))) << (16 * e);
            }
            v[h] = p;
        }
        bsh[ks][nt][ln] = make_uint2(v[0], v[1]);
    }
    // Zero the pad words (50,51) of the A stage once; never overwritten.
    { const int r = lane >> 1, w = 50 + (lane & 1);
      whi[r * WARP_WORDS + w] = 0; wlo[r * WARP_WORDS + w] = 0; }
    __syncthreads();

    for (int tile = blockIdx.x; tile < ntiles; tile += GRID) {
        const int r0 = tile * MT + wid * 16 + g;

        // Stage this warp's 16 contiguous rows: coalesced LDG.128, split, STS.
        __syncwarp();
        {
            const float4* const xr4 = reinterpret_cast<const float4*>(
                x + (size_t)(tile * MT + wid * 16) * NFFT);
#pragma unroll
            for (int it = 0; it < 13; ++it) {
                const int idx = it * 32 + lane;
                if (idx < 400) {
                    const float4 v = xr4[idx];
                    uint32_t h0, l0, h1, l1;
                    split2(make_float2(v.x, v.y), h0, l0);
                    split2(make_float2(v.z, v.w), h1, l1);
                    const int r = idx / 25, wo = 2 * (idx % 25);
                    uint32_t* hp = whi + r * WARP_WORDS + wo;
                    hp[0] = h0; hp[1] = h1;
                    uint32_t* lp = wlo + r * WARP_WORDS + wo;
                    lp[0] = l0; lp[1] = l1;
                }
            }
        }
        __syncwarp();

        uint32_t accP[NNT][4], accM[NNT][4];
#pragma unroll
        for (int nt = 0; nt < NNT; ++nt)
#pragma unroll
            for (int q = 0; q < 4; ++q) { accP[nt][q] = 0u; accM[nt][q] = 0u; }

#pragma unroll
        for (int ks = 0; ks < NKS; ++ks) {
            uint4 ah, al;
            const uint32_t* hp = whi + 8 * ks + tg;
            const uint32_t* lp = wlo + 8 * ks + tg;
            ah.x = hp[g * WARP_WORDS];       ah.y = hp[(g + 8) * WARP_WORDS];
            al.x = lp[g * WARP_WORDS];       al.y = lp[(g + 8) * WARP_WORDS];
            if (ks < 6) {
                ah.z = hp[g * WARP_WORDS + 4]; ah.w = hp[(g + 8) * WARP_WORDS + 4];
                al.z = lp[g * WARP_WORDS + 4]; al.w = lp[(g + 8) * WARP_WORDS + 4];
            } else { ah.z = ah.w = al.z = al.w = 0u; }

            uint2 b[NNT];
#pragma unroll
            for (int nt = 0; nt < NNT; ++nt) b[nt] = bsh[ks][nt][lane];

#pragma unroll
            for (int nt = 0; nt < NNT; ++nt) {
                mma16816(accP[nt], ah, b[nt]);
                mma16816(accP[nt], al, b[nt]);
            }
            // A- = x*(-1)^k: flip sign of odd-k (high) halves.
            ah.x ^= 0x80000000u; ah.y ^= 0x80000000u;
            ah.z ^= 0x80000000u; ah.w ^= 0x80000000u;
            al.x ^= 0x80000000u; al.y ^= 0x80000000u;
            al.z ^= 0x80000000u; al.w ^= 0x80000000u;
#pragma unroll
            for (int nt = 0; nt < NNT; ++nt) {
                mma16816(accM[nt], ah, b[nt]);
                mma16816(accM[nt], al, b[nt]);
            }
        }

        // ---- Epilogue ----
        float sg = 0.f, sh = 0.f;
        float* const outr  = xfft + (size_t)r0 * NFFT;
        float* const outr8 = outr + 8 * NFFT;

        // P variant: folded col c -> out col c (re, c<26) or c+24 (im region).
        // Even base offsets -> aligned float2 stores.
#pragma unroll
        for (int nt = 0; nt < NNT; ++nt) {
            const int c0 = 8 * nt + 2 * tg;
            const float f0 = __uint_as_float(accP[nt][0]);
            const float f1 = __uint_as_float(accP[nt][1]);
            const float f2 = __uint_as_float(accP[nt][2]);
            const float f3 = __uint_as_float(accP[nt][3]);
            sg += f0 * f0 + f1 * f1;             // padding cols are exact zeros
            sh += f2 * f2 + f3 * f3;
            if (c0 < 52) {
                const int C = (c0 < 26) ? c0 : c0 + 24;
                st2(outr + C, f0, f1);
                st2(outr8 + C, f2, f3);
            }
        }
        // M variant (mirror): re c (1..24) -> col 50-c; im c (27..50) -> col
        // 126-c negated. Odd-offset targets -> scalar stores. c=0,26 invalid;
        // c=25,51 deduped (owned by P).
#pragma unroll
        for (int nt = 0; nt < NNT; ++nt) {
            const int c0 = 8 * nt + 2 * tg;
            const float f0 = __uint_as_float(accM[nt][0]);
            const float f1 = __uint_as_float(accM[nt][1]);
            const float f2 = __uint_as_float(accM[nt][2]);
            const float f3 = __uint_as_float(accM[nt][3]);
            if (nt == 0 && tg == 0) {               // c=0 invalid; c=1 -> col 49
                outr[49] = f1;  outr8[49] = f3;
                sg += f1 * f1;  sh += f3 * f3;
            } else if (nt < 3 || (nt == 3 && tg == 0 && false)) {
                // re region general: c0 in 2..22 -> cols 50-c0 (f0), 49-c0 (f1)
                outr[50 - c0] = f0;  outr[49 - c0] = f1;
                outr8[50 - c0] = f2; outr8[49 - c0] = f3;
                sg += f0 * f0 + f1 * f1;  sh += f2 * f2 + f3 * f3;
            } else if (nt == 3) {
                if (tg == 0) {                      // c=24 -> col 26; c=25 dup
                    outr[26] = f0;  outr8[26] = f2;
                    sg += f0 * f0;  sh += f2 * f2;
                } else if (tg == 1) {               // c=26 invalid; c=27 -> col 99
                    outr[99] = -f1;  outr8[99] = -f3;
                    sg += f1 * f1;   sh += f3 * f3;
                } else {                            // im: cols 126-c0, 125-c0
                    outr[126 - c0] = -f0;  outr[125 - c0] = -f1;
                    outr8[126 - c0] = -f2; outr8[125 - c0] = -f3;
                    sg += f0 * f0 + f1 * f1;  sh += f2 * f2 + f3 * f3;
                }
            } else if (nt <= 5) {                   // im general
                outr[126 - c0] = -f0;  outr[125 - c0] = -f1;
                outr8[126 - c0] = -f2; outr8[125 - c0] = -f3;
                sg += f0 * f0 + f1 * f1;  sh += f2 * f2 + f3 * f3;
            } else {                                // nt == 6
                if (tg == 0) {                      // c=48,49 -> cols 78,77
                    outr[78] = -f0;  outr[77] = -f1;
                    outr8[78] = -f2; outr8[77] = -f3;
                    sg += f0 * f0 + f1 * f1;  sh += f2 * f2 + f3 * f3;
                } else if (tg == 1) {               // c=50 -> col 76; c=51 dup
                    outr[76] = -f0;  outr8[76] = -f2;
                    sg += f0 * f0;   sh += f2 * f2;
                }                                    // tg>=2: padding, acc==0
            }
        }

        sg += __shfl_xor_sync(0xffffffffu, sg, 1);
        sg += __shfl_xor_sync(0xffffffffu, sg, 2);
        sh += __shfl_xor_sync(0xffffffffu, sh, 1);
        sh += __shfl_xor_sync(0xffffffffu, sh, 2);
        if (tg == 0) {
            logp[r0]     = -0.5f * sg - 91.893853320467274f;
            logp[r0 + 8] = -0.5f * sh - 91.893853320467274f;
        }
    }
}

extern "C" void kernel_launch(void* const* d_in, const int* in_sizes, int n_in,
                              void* d_out, int out_size) {
    const float* x = (const float*)d_in[0];
    const int B = in_sizes[0] / NFFT;              // 262144
    float* xf = (float*)d_out;
    float* lp = xf + (size_t)B * NFFT;
    cudaFuncSetAttribute(dft_mma, cudaFuncAttributeMaxDynamicSharedMemorySize, SMEM_TOTAL);
    dft_mma<<<GRID, BT, SMEM_TOTAL>>>(x, xf, lp, B / MT);
}

// round 10
// speedup vs baseline: 1.0004x; 1.0004x over previous
#include <cuda_runtime.h>
#include <cuda_fp16.h>
#include <cstdint>

// DFT_10316511445664 — batched 100-pt DFT as folded fp16 split mma.sync GEMM.
// out[B,100] = x @ W. Column symmetry: with A- = x*(-1)^k (sign-flip of odd-k
// halves), the 52-col folded B yields bins j (A+) and 50-j (A-), halving B-LDS.
// A staged per-warp in smem (coalesced LDG.128, conflict-free LDS.32 frags).
// Mirror-side (M) outputs land on odd column offsets -> scalar stores.

#define NFFT 100
#define MT   128
#define BT   256
#define GRID 444       // 148 SMs * 3 CTAs
#define NKS  7
#define NNT  7         // folded 52 cols padded to 56

// smem: [0,12544) B frags uint2[NKS][NNT][32]; then per-warp A stage 6656B
// (hi [16][52] u32 f16x2-words, lo at +832 words; words 50,51 = zero pad).
#define B_BYTES    12544
#define WARP_WORDS 52
#define SMEM_TOTAL (B_BYTES + 8 * 6656)

__device__ __forceinline__ float wvalf(int k, int c) {
    if (k >= NFFT || c >= 52) return 0.f;
    const bool re = (c < 26);
    const int j = re ? c : c - 26;
    const int m = (k * j) % 100;
    float s, cs;
    sincospif((float)m * 0.02f, &s, &cs);
    float t = re ? cs : -s;            // re: cos ; im: -sin
    if (k & 1) t = -t;                 // fftshift (-1)^k
    return t * 0.01f;                  // 1/N_FFT
}

__device__ __forceinline__ void mma16816(uint32_t* d, const uint4& a, const uint2& b) {
    asm volatile(
        "mma.sync.aligned.m16n8k16.row.col.f32.f16.f16.f32 "
        "{%0,%1,%2,%3}, {%4,%5,%6,%7}, {%8,%9}, {%0,%1,%2,%3};"
        : "+r"(d[0]), "+r"(d[1]), "+r"(d[2]), "+r"(d[3])
        : "r"(a.x), "r"(a.y), "r"(a.z), "r"(a.w), "r"(b.x), "r"(b.y));
}

// float2 -> fp16x2 hi + fp16x2 lo (low 16 bits = first/even element)
__device__ __forceinline__ void split2(float2 v, uint32_t& hi, uint32_t& lo) {
    asm("cvt.rn.f16x2.f32 %0, %1, %2;" : "=r"(hi) : "f"(v.y), "f"(v.x));
    float h0, h1;
    asm("{ .reg .b16 a, b; mov.b32 {a, b}, %2; cvt.f32.f16 %0, a; cvt.f32.f16 %1, b; }"
        : "=f"(h0), "=f"(h1) : "r"(hi));
    asm("cvt.rn.f16x2.f32 %0, %1, %2;" : "=r"(lo) : "f"(v.y - h1), "f"(v.x - h0));
}

__device__ __forceinline__ void st2(float* p, float a, float b) {
    *reinterpret_cast<float2*>(p) = make_float2(a, b);
}

__global__ __launch_bounds__(BT, 3) void dft_mma(const float* __restrict__ x,
                                                 float* __restrict__ xfft,
                                                 float* __restrict__ logp,
                                                 int ntiles) {
    extern __shared__ char smem[];
    uint2 (*bsh)[NNT][32] = reinterpret_cast<uint2 (*)[NNT][32]>(smem);

    const int tid  = threadIdx.x;
    const int wid  = tid >> 5;
    const int lane = tid & 31;
    const int g    = lane >> 2, tg = lane & 3;

    uint32_t* const whi = reinterpret_cast<uint32_t*>(smem + B_BYTES + wid * 6656);
    uint32_t* const wlo = whi + 16 * WARP_WORDS;

    // Build folded B fragments in-CTA (fp32 sincospi; error << fp16 rounding).
    for (int i = tid; i < NKS * NNT * 32; i += BT) {
        const int ln = i & 31, t = i >> 5;
        const int nt = t % NNT, ks = t / NNT;
        const int c = 8 * nt + (ln >> 2), tt = ln & 3;
        uint32_t v[2];
#pragma unroll
        for (int h = 0; h < 2; ++h) {
            uint32_t p = 0;
#pragma unroll
            for (int e = 0; e < 2; ++e) {
                const int k = 16 * ks + 2 * tt + 8 * h + e;
                p |= (uint32_t)__half_as_ushort(__float2half_rn(wvalf(k, c))) << (16 * e);
            }
            v[h] = p;
        }
        bsh[ks][nt][ln] = make_uint2(v[0], v[1]);
    }
    // Zero the pad words (50,51) of the A stage once; never overwritten.
    { const int r = lane >> 1, w = 50 + (lane & 1);
      whi[r * WARP_WORDS + w] = 0; wlo[r * WARP_WORDS + w] = 0; }
    __syncthreads();

    for (int tile = blockIdx.x; tile < ntiles; tile += GRID) {
        const int r0 = tile * MT + wid * 16 + g;

        // Stage this warp's 16 contiguous rows: coalesced LDG.128, split, STS.
        __syncwarp();
        {
            const float4* const xr4 = reinterpret_cast<const float4*>(
                x + (size_t)(tile * MT + wid * 16) * NFFT);
#pragma unroll
            for (int it = 0; it < 13; ++it) {
                const int idx = it * 32 + lane;
                if (idx < 400) {
                    const float4 v = xr4[idx];
                    uint32_t h0, l0, h1, l1;
                    split2(make_float2(v.x, v.y), h0, l0);
                    split2(make_float2(v.z, v.w), h1, l1);
                    const int r = idx / 25, wo = 2 * (idx % 25);
                    uint32_t* hp = whi + r * WARP_WORDS + wo;
                    hp[0] = h0; hp[1] = h1;
                    uint32_t* lp = wlo + r * WARP_WORDS + wo;
                    lp[0] = l0; lp[1] = l1;
                }
            }
        }
        __syncwarp();

        uint32_t accP[NNT][4], accM[NNT][4];
#pragma unroll
        for (int nt = 0; nt < NNT; ++nt)
#pragma unroll
            for (int q = 0; q < 4; ++q) { accP[nt][q] = 0u; accM[nt][q] = 0u; }

#pragma unroll
        for (int ks = 0; ks < NKS; ++ks) {
            uint4 ah, al;
            const uint32_t* hp = whi + 8 * ks + tg;
            const uint32_t* lp = wlo + 8 * ks + tg;
            ah.x = hp[g * WARP_WORDS];       ah.y = hp[(g + 8) * WARP_WORDS];
            al.x = lp[g * WARP_WORDS];       al.y = lp[(g + 8) * WARP_WORDS];
            if (ks < 6) {
                ah.z = hp[g * WARP_WORDS + 4]; ah.w = hp[(g + 8) * WARP_WORDS + 4];
                al.z = lp[g * WARP_WORDS + 4]; al.w = lp[(g + 8) * WARP_WORDS + 4];
            } else { ah.z = ah.w = al.z = al.w = 0u; }

            uint2 b[NNT];
#pragma unroll
            for (int nt = 0; nt < NNT; ++nt) b[nt] = bsh[ks][nt][lane];

#pragma unroll
            for (int nt = 0; nt < NNT; ++nt) {
                mma16816(accP[nt], ah, b[nt]);
                mma16816(accP[nt], al, b[nt]);
            }
            // A- = x*(-1)^k: flip sign of odd-k (high) halves.
            ah.x ^= 0x80000000u; ah.y ^= 0x80000000u;
            ah.z ^= 0x80000000u; ah.w ^= 0x80000000u;
            al.x ^= 0x80000000u; al.y ^= 0x80000000u;
            al.z ^= 0x80000000u; al.w ^= 0x80000000u;
#pragma unroll
            for (int nt = 0; nt < NNT; ++nt) {
                mma16816(accM[nt], ah, b[nt]);
                mma16816(accM[nt], al, b[nt]);
            }
        }

        // ---- Epilogue ----
        float sg = 0.f, sh = 0.f;
        float* const outr  = xfft + (size_t)r0 * NFFT;
        float* const outr8 = outr + 8 * NFFT;

        // P variant: folded col c -> out col c (re, c<26) or c+24 (im region).
        // Even base offsets -> aligned float2 stores.
#pragma unroll
        for (int nt = 0; nt < NNT; ++nt) {
            const int c0 = 8 * nt + 2 * tg;
            const float f0 = __uint_as_float(accP[nt][0]);
            const float f1 = __uint_as_float(accP[nt][1]);
            const float f2 = __uint_as_float(accP[nt][2]);
            const float f3 = __uint_as_float(accP[nt][3]);
            sg += f0 * f0 + f1 * f1;             // padding cols are exact zeros
            sh += f2 * f2 + f3 * f3;
            if (c0 < 52) {
                const int C = (c0 < 26) ? c0 : c0 + 24;
                st2(outr + C, f0, f1);
                st2(outr8 + C, f2, f3);
            }
        }
        // M variant (mirror): re c (1..24) -> col 50-c; im c (27..50) -> col
        // 126-c negated. Odd-offset targets -> scalar stores. c=0,26 invalid;
        // c=25,51 deduped (owned by P).
#pragma unroll
        for (int nt = 0; nt < NNT; ++nt) {
            const int c0 = 8 * nt + 2 * tg;
            const float f0 = __uint_as_float(accM[nt][0]);
            const float f1 = __uint_as_float(accM[nt][1]);
            const float f2 = __uint_as_float(accM[nt][2]);
            const float f3 = __uint_as_float(accM[nt][3]);
            if (nt == 0 && tg == 0) {               // c=0 invalid; c=1 -> col 49
                outr[49] = f1;  outr8[49] = f3;
                sg += f1 * f1;  sh += f3 * f3;
            } else if (nt < 3 || (nt == 3 && tg == 0 && false)) {
                // re region general: c0 in 2..22 -> cols 50-c0 (f0), 49-c0 (f1)
                outr[50 - c0] = f0;  outr[49 - c0] = f1;
                outr8[50 - c0] = f2; outr8[49 - c0] = f3;
                sg += f0 * f0 + f1 * f1;  sh += f2 * f2 + f3 * f3;
            } else if (nt == 3) {
                if (tg == 0) {                      // c=24 -> col 26; c=25 dup
                    outr[26] = f0;  outr8[26] = f2;
                    sg += f0 * f0;  sh += f2 * f2;
                } else if (tg == 1) {               // c=26 invalid; c=27 -> col 99
                    outr[99] = -f1;  outr8[99] = -f3;
                    sg += f1 * f1;   sh += f3 * f3;
                } else {                            // im: cols 126-c0, 125-c0
                    outr[126 - c0] = -f0;  outr[125 - c0] = -f1;
                    outr8[126 - c0] = -f2; outr8[125 - c0] = -f3;
                    sg += f0 * f0 + f1 * f1;  sh += f2 * f2 + f3 * f3;
                }
            } else if (nt <= 5) {                   // im general
                outr[126 - c0] = -f0;  outr[125 - c0] = -f1;
                outr8[126 - c0] = -f2; outr8[125 - c0] = -f3;
                sg += f0 * f0 + f1 * f1;  sh += f2 * f2 + f3 * f3;
            } else {                                // nt == 6
                if (tg == 0) {                      // c=48,49 -> cols 78,77
                    outr[78] = -f0;  outr[77] = -f1;
                    outr8[78] = -f2; outr8[77] = -f3;
                    sg += f0 * f0 + f1 * f1;  sh += f2 * f2 + f3 * f3;
                } else if (tg == 1) {               // c=50 -> col 76; c=51 dup
                    outr[76] = -f0;  outr8[76] = -f2;
                    sg += f0 * f0;   sh += f2 * f2;
                }                                    // tg>=2: padding, acc==0
            }
        }

        sg += __shfl_xor_sync(0xffffffffu, sg, 1);
        sg += __shfl_xor_sync(0xffffffffu, sg, 2);
        sh += __shfl_xor_sync(0xffffffffu, sh, 1);
        sh += __shfl_xor_sync(0xffffffffu, sh, 2);
        if (tg == 0) {
            logp[r0]     = -0.5f * sg - 91.893853320467274f;
            logp[r0 + 8] = -0.5f * sh - 91.893853320467274f;
        }
    }
}

extern "C" void kernel_launch(void* const* d_in, const int* in_sizes, int n_in,
                              void* d_out, int out_size) {
    const float* x = (const float*)d_in[0];
    const int B = in_sizes[0] / NFFT;              // 262144
    float* xf = (float*)d_out;
    float* lp = xf + (size_t)B * NFFT;
    cudaFuncSetAttribute(dft_mma, cudaFuncAttributeMaxDynamicSharedMemorySize, SMEM_TOTAL);
    dft_mma<<<GRID, BT, SMEM_TOTAL>>>(x, xf, lp, B / MT);
}